// round 15
// baseline (speedup 1.0000x reference)
#include <cuda_runtime.h>
#include <math.h>

// PMXELoss: NQ=4096 queries, NS=16384 supports, D=128, C=64
#define NQ_   4096
#define NS_   16384
#define D_    128
#define C_    64
#define INFV  1000.0f

#define QPB   4                // queries per k_query block (1 per warp)
#define NBLK  (NQ_ / QPB)      // 1024 blocks

// Static device scratch (no allocations allowed)
__device__ float4 g_muI[C_ * 32];   // FINAL per-class mu, interleaved chunk layout
__device__ float  g_mn[C_];         // ||mu_c||^2
__device__ float  g_cntf[C_];       // per-class counts (float)
__device__ float  g_inv[C_];        // 1/(cnt-1)
__device__ float  g_A[C_];          // -0.5*cnt/(cnt-1)
__device__ float  g_B[C_];          // -0.5*SS/(cnt-1)
__device__ float  g_bsum[NBLK];     // per-block partial loss sums
__device__ int    g_done = 0;       // last-block counter (self-resetting)

__device__ __forceinline__ float dot4(float4 a, float4 b) {
    return a.x * b.x + a.y * b.y + a.z * b.z + a.w * b.w;
}
__device__ __forceinline__ float fma4(float4 m, float4 v, float acc) {
    return fmaf(m.w, v.w, fmaf(m.z, v.z, fmaf(m.y, v.y, fmaf(m.x, v.x, acc))));
}

// ---------------------------------------------------------------------------
// 64 blocks x 1024 threads: one block per class. 32 warps x 512 rows each,
// all y-labels prefetched as int4. Writes FINAL mu (interleaved layout) and
// all derived per-class parameters, so k_query has zero prologue work.
__global__ void __launch_bounds__(1024) k_classsum(const float4* __restrict__ xs4,
                                                   const int*    __restrict__ ys) {
    const int c    = blockIdx.x;
    const int lane = threadIdx.x & 31;
    const int w    = threadIdx.x >> 5;          // 0..31

    __shared__ float4 s_acc[32][32];
    __shared__ float  s_ss[32];
    __shared__ int    s_cnt[32];

    const int base  = w * 512;                  // 512 rows per warp
    const int4* ys4 = (const int4*)ys;
    const int ybase = base >> 2;
    int4 ybuf[4];
#pragma unroll
    for (int i = 0; i < 4; ++i) ybuf[i] = ys4[ybase + i * 32 + lane];

    float4 acc = make_float4(0.f, 0.f, 0.f, 0.f);
    float  ss  = 0.f;
    int    cnt = 0;

#pragma unroll
    for (int b = 0; b < 4; ++b) {
        int4 yv = ybuf[b];
        int  j0 = base + b * 128;
        unsigned m0 = __ballot_sync(0xffffffffu, yv.x == c);
        unsigned m1 = __ballot_sync(0xffffffffu, yv.y == c);
        unsigned m2 = __ballot_sync(0xffffffffu, yv.z == c);
        unsigned m3 = __ballot_sync(0xffffffffu, yv.w == c);
        cnt += __popc(m0) + __popc(m1) + __popc(m2) + __popc(m3);
#pragma unroll
        for (int k = 0; k < 4; ++k) {           // component k -> row j0+4*bit+k
            unsigned m = (k == 0) ? m0 : (k == 1) ? m1 : (k == 2) ? m2 : m3;
            while (m) {
                int bb = __ffs(m) - 1; m &= m - 1;
                float4 vv = xs4[(j0 + 4 * bb + k) * 32 + lane];  // 512B row
                acc.x += vv.x; acc.y += vv.y; acc.z += vv.z; acc.w += vv.w;
                ss = fma4(vv, vv, ss);
            }
        }
    }
    s_acc[w][lane] = acc;
#pragma unroll
    for (int o = 16; o; o >>= 1) ss += __shfl_xor_sync(0xffffffffu, ss, o);
    if (lane == 0) { s_ss[w] = ss; s_cnt[w] = cnt; }   // cnt is warp-uniform
    __syncthreads();

    if (w == 0) {
        float4 t = s_acc[0][lane];
#pragma unroll
        for (int ww = 1; ww < 32; ++ww) {
            float4 u = s_acc[ww][lane];
            t.x += u.x; t.y += u.y; t.z += u.z; t.w += u.w;
        }
        // interleaved layout: chunk k -> slot ((k&1)<<4) | (k>>1)
        g_muI[c * 32 + ((lane & 1) << 4) + (lane >> 1)] = t;

        float mn  = dot4(t, t);
        float sst = s_ss[lane];
        int   cn  = s_cnt[lane];
#pragma unroll
        for (int o = 16; o; o >>= 1) {
            mn  += __shfl_xor_sync(0xffffffffu, mn, o);
            sst += __shfl_xor_sync(0xffffffffu, sst, o);
            cn  += __shfl_xor_sync(0xffffffffu, cn, o);
        }
        if (lane == 0) {
            float cnf = (float)cn;
            float iv  = 1.f / (cnf - 1.f);
            g_mn[c]   = mn;
            g_cntf[c] = cnf;
            g_inv[c]  = iv;
            g_A[c]    = -0.5f * cnf * iv;
            g_B[c]    = -0.5f * sst * iv;
        }
    }
}

// ---------------------------------------------------------------------------
// 1024 blocks x 128 threads: ONE query per warp. Each 16-lane half owns 32
// classes; lane i handles dims [8i, 8i+8). Accumulators drop to v[32] (~75
// regs -> 6 CTAs/SM resident). mu read through L1 (32KB tile stays hot).
// Epilogue: 4-stage halving exchange (30 shfl), division-free normalized
// logits, analytic pos_logit, full-warp LSE, fused mean.
__global__ void __launch_bounds__(128, 6) k_query(
    const float4* __restrict__ xq4, const int* __restrict__ yq,
    const float4* __restrict__ xs4, const int* __restrict__ ys,
    const int* __restrict__ pos, float* __restrict__ out)
{
    const int tid  = threadIdx.x;
    const int lane = tid & 31;
    const int w    = tid >> 5;          // warp 0..3
    const int h    = lane >> 4;         // class-half 0/1
    const int i    = lane & 15;         // dim-split (dims 8i .. 8i+7)
    const int q    = blockIdx.x * QPB + w;

    __shared__ float s_wsum[QPB];
    __shared__ float s_f[128];
    __shared__ int   s_last;

    // ---- per-query loads (both halves load the same dims; L1 dedup) ----
    float4 xr0 = xq4[q * 32 + 2 * i];
    float4 xr1 = xq4[q * 32 + 2 * i + 1];
    const int p   = pos[q];
    const int cq  = ys[p];
    const int yqi = yq[q];
    float4 sp0 = xs4[p * 32 + 2 * i];
    float4 sp1 = xs4[p * 32 + 2 * i + 1];

    // ---- hot loop: 32 class dots per lane (half h owns classes 32h..32h+31) ----
    const int cb = h << 5;
    float v[32];
#pragma unroll
    for (int c2 = 0; c2 < 32; ++c2) {
        float4 m0 = __ldg(&g_muI[(cb + c2) * 32 + i]);
        float4 m1 = __ldg(&g_muI[(cb + c2) * 32 + 16 + i]);
        v[c2] = fma4(m1, xr1, fma4(m0, xr0, 0.f));
    }

    // ---- recursive-halving exchange within each 16-lane half: 30 shfl ----
#pragma unroll
    for (int s = 0; s < 4; ++s) {
        const int o  = 1 << s;
        const int hn = 16 >> s;                 // 16,8,4,2
        const bool up = (i & o) != 0;
#pragma unroll
        for (int j = 0; j < hn; ++j) {
            float send = up ? v[j] : v[j + hn];
            float keep = up ? v[j + hn] : v[j];
            v[j] = keep + __shfl_xor_sync(0xffffffffu, send, o);
        }
    }
    // lane owns classes clb + j, j in {0,1}
    const int clb = cb + (((i & 1) << 4) | ((i & 2) << 2) | (i & 4) | ((i & 8) >> 2));

    // ---- per-query scalars: qq and (pp - 2*dp) in two half-reductions ----
    float qq  = dot4(xr0, xr0) + dot4(xr1, xr1);
    float tpd = dot4(sp0, sp0) + dot4(sp1, sp1)
              - 2.f * (dot4(xr0, sp0) + dot4(xr1, sp1));
#pragma unroll
    for (int o = 1; o <= 8; o <<= 1) {
        qq  += __shfl_xor_sync(0xffffffffu, qq, o);
        tpd += __shfl_xor_sync(0xffffffffu, tpd, o);
    }

    // normalized logits for owned classes; extract raw dot(x, mu_cq)
    float dm = 0.f;
    float nv0, nv1;
    {
        int c0 = clb, c1 = clb + 1;
        if (c0 == cq) dm = v[0];
        if (c1 == cq) dm = v[1];
        nv0 = fmaf(v[0], __ldg(&g_inv[c0]), fmaf(__ldg(&g_A[c0]), qq, __ldg(&g_B[c0])));
        nv1 = fmaf(v[1], __ldg(&g_inv[c1]), fmaf(__ldg(&g_A[c1]), qq, __ldg(&g_B[c1])));
    }
#pragma unroll
    for (int o = 1; o <= 16; o <<= 1) dm += __shfl_xor_sync(0xffffffffu, dm, o);

    // exact (i, pos_i) pair logit + bucket patch
    float pair  = -0.5f * fmaxf(qq + tpd, 0.f);
    float delta = ((__ldg(&g_cntf[yqi]) > 1.5f) ? -INFV : 0.f) - pair;
    float patch = delta * __ldg(&g_inv[cq]);
    if (clb == cq)     nv0 += patch;
    if (clb + 1 == cq) nv1 += patch;

    // analytic pos_logit: ||x - proto||^2 = (e^2 qq - 2 e dm + ||mu||^2)/den^2
    float cnq  = __ldg(&g_cntf[cq]);
    float den  = fmaxf(cnq - 1.f, 0.1f);
    float e    = den + 1.f;
    float d2   = (e * e * qq - 2.f * e * dm + __ldg(&g_mn[cq])) / (den * den);
    float plog = -sqrtf(fmaxf(d2, 0.f));

    // ---- LSE over 64 classes (2 local + full-warp butterfly) ----
    float mx = fmaxf(nv0, nv1);
#pragma unroll
    for (int o = 1; o <= 16; o <<= 1)
        mx = fmaxf(mx, __shfl_xor_sync(0xffffffffu, mx, o));
    float ex = expf(nv0 - mx) + expf(nv1 - mx);
#pragma unroll
    for (int o = 1; o <= 16; o <<= 1)
        ex += __shfl_xor_sync(0xffffffffu, ex, o);
    float res = (mx + logf(ex)) - plog;

    // ---- fused mean: block -> last-block ----
    if (lane == 0) s_wsum[w] = res;
    __syncthreads();

    if (tid == 0) {
        g_bsum[blockIdx.x] = s_wsum[0] + s_wsum[1] + s_wsum[2] + s_wsum[3];
        __threadfence();
        int old = atomicAdd(&g_done, 1);
        s_last = (old == NBLK - 1);
    }
    __syncthreads();
    if (s_last) {
        __threadfence();
        float acc = 0.f;
#pragma unroll
        for (int it = 0; it < NBLK / 128; ++it) {
            float u;
            asm volatile("ld.global.cg.f32 %0, [%1];"
                         : "=f"(u) : "l"(&g_bsum[tid + it * 128]));
            acc += u;
        }
        s_f[tid] = acc;
        __syncthreads();
#pragma unroll
        for (int o = 64; o; o >>= 1) {
            if (tid < o) s_f[tid] += s_f[tid + o];
            __syncthreads();
        }
        if (tid == 0) {
            out[0] = s_f[0] * (1.0f / (float)NQ_);
            g_done = 0;                         // reset for next graph replay
        }
    }
}

// ---------------------------------------------------------------------------
extern "C" void kernel_launch(void* const* d_in, const int* in_sizes, int n_in,
                              void* d_out, int out_size) {
    const float4* xq4 = (const float4*)d_in[0];   // [NQ, D] f32
    const int*    yqp = (const int*)   d_in[1];   // [NQ]    i32
    const float4* xs4 = (const float4*)d_in[2];   // [NS, D] f32
    const int*    ysp = (const int*)   d_in[3];   // [NS]    i32
    const int*    pop = (const int*)   d_in[4];   // [NQ]    i32
    (void)in_sizes; (void)n_in; (void)out_size;

    k_classsum<<<C_, 1024>>>(xs4, ysp);
    k_query<<<NBLK, 128>>>(xq4, yqp, xs4, ysp, pop, (float*)d_out);
}

// round 16
// speedup vs baseline: 1.1008x; 1.1008x over previous
#include <cuda_runtime.h>
#include <math.h>

// PMXELoss: NQ=4096 queries, NS=16384 supports, D=128, C=64
#define NQ_   4096
#define NS_   16384
#define D_    128
#define C_    64
#define INFV  1000.0f

#define QPB   4                  // queries per k_query block (2 warp-pairs)
#define NBLK  (NQ_ / QPB)        // 1024 blocks
#define CSQ   4                  // classsum blocks per class
#define CSBLK (C_ * CSQ)         // 256 blocks

// Static device scratch (no allocations allowed)
__device__ float4 g_musp[CSBLK * 32]; // per-(class,quarter) partial mu
__device__ float  g_ssp[CSBLK];       // partial sum ||xs||^2
__device__ int    g_cntp[CSBLK];      // partial counts
__device__ int    g_cdone[C_];        // per-class arrival counters (self-reset)
__device__ float4 g_muI[C_ * 32];     // FINAL mu, interleaved chunk layout
__device__ float  g_mn[C_];           // ||mu_c||^2
__device__ float  g_cntf[C_];         // counts (float)
__device__ float  g_inv[C_];          // 1/(cnt-1)
__device__ float  g_A[C_];            // -0.5*cnt/(cnt-1)
__device__ float  g_B[C_];            // -0.5*SS/(cnt-1)
__device__ float  g_bsum[NBLK];       // per-block partial loss sums
__device__ int    g_done = 0;         // last-block counter (self-reset)

__device__ __forceinline__ float dot4(float4 a, float4 b) {
    return a.x * b.x + a.y * b.y + a.z * b.z + a.w * b.w;
}
__device__ __forceinline__ float fma4(float4 m, float4 v, float acc) {
    return fmaf(m.w, v.w, fmaf(m.z, v.z, fmaf(m.y, v.y, fmaf(m.x, v.x, acc))));
}

// ---------------------------------------------------------------------------
// 256 blocks x 512 threads: block = (class c = bid>>2, quarter = bid&3).
// 16 warps x 256 rows each, labels prefetched as int4. Each block writes a
// partial; the LAST block per class (atomic counter) combines all 4 quarters
// and emits final interleaved mu + derived per-class parameters.
__global__ void __launch_bounds__(512) k_classsum(const float4* __restrict__ xs4,
                                                  const int*    __restrict__ ys) {
    const int c    = blockIdx.x >> 2;
    const int qt   = blockIdx.x & 3;
    const int lane = threadIdx.x & 31;
    const int w    = threadIdx.x >> 5;          // 0..15

    __shared__ float4 s_acc[16][32];
    __shared__ float  s_ss[16];
    __shared__ int    s_cnt[16];

    const int base  = qt * (NS_ / 4) + w * 256; // 256 rows per warp
    const int4* ys4 = (const int4*)ys;
    const int ybase = base >> 2;
    int4 y0 = ys4[ybase + lane];                // rows [base, base+128)
    int4 y1 = ys4[ybase + 32 + lane];           // rows [base+128, base+256)

    float4 acc = make_float4(0.f, 0.f, 0.f, 0.f);
    float  ss  = 0.f;
    int    cnt = 0;

#pragma unroll
    for (int b = 0; b < 2; ++b) {
        int4 yv = b ? y1 : y0;
        int  j0 = base + b * 128;
        unsigned m0 = __ballot_sync(0xffffffffu, yv.x == c);
        unsigned m1 = __ballot_sync(0xffffffffu, yv.y == c);
        unsigned m2 = __ballot_sync(0xffffffffu, yv.z == c);
        unsigned m3 = __ballot_sync(0xffffffffu, yv.w == c);
        cnt += __popc(m0) + __popc(m1) + __popc(m2) + __popc(m3);
#pragma unroll
        for (int k = 0; k < 4; ++k) {           // component k -> row j0+4*bit+k
            unsigned m = (k == 0) ? m0 : (k == 1) ? m1 : (k == 2) ? m2 : m3;
            while (m) {
                int bb = __ffs(m) - 1; m &= m - 1;
                float4 vv = xs4[(j0 + 4 * bb + k) * 32 + lane];  // 512B row
                acc.x += vv.x; acc.y += vv.y; acc.z += vv.z; acc.w += vv.w;
                ss = fma4(vv, vv, ss);
            }
        }
    }
    s_acc[w][lane] = acc;
#pragma unroll
    for (int o = 16; o; o >>= 1) ss += __shfl_xor_sync(0xffffffffu, ss, o);
    if (lane == 0) { s_ss[w] = ss; s_cnt[w] = cnt; }   // cnt is warp-uniform
    __syncthreads();

    if (w == 0) {
        float4 t = s_acc[0][lane];
#pragma unroll
        for (int ww = 1; ww < 16; ++ww) {
            float4 u = s_acc[ww][lane];
            t.x += u.x; t.y += u.y; t.z += u.z; t.w += u.w;
        }
        g_musp[blockIdx.x * 32 + lane] = t;

        float sst = (lane < 16) ? s_ss[lane] : 0.f;
        int   cn  = (lane < 16) ? s_cnt[lane] : 0;
#pragma unroll
        for (int o = 8; o; o >>= 1) {
            sst += __shfl_xor_sync(0xffffffffu, sst, o);
            cn  += __shfl_xor_sync(0xffffffffu, cn, o);
        }
        if (lane == 0) { g_ssp[blockIdx.x] = sst; g_cntp[blockIdx.x] = cn; }

        // last block of this class combines all quarters (order-fixed, det.)
        int old = 0;
        if (lane == 0) {
            __threadfence();
            old = atomicAdd(&g_cdone[c], 1);
        }
        int last = __shfl_sync(0xffffffffu, old, 0) == (CSQ - 1);
        if (last) {
            __threadfence();
            float4 tt = make_float4(0.f, 0.f, 0.f, 0.f);
#pragma unroll
            for (int q2 = 0; q2 < CSQ; ++q2) {
                float4 u = __ldcg(&g_musp[(c * CSQ + q2) * 32 + lane]);
                tt.x += u.x; tt.y += u.y; tt.z += u.z; tt.w += u.w;
            }
            // interleaved layout: chunk k -> slot ((k&1)<<4) | (k>>1)
            g_muI[c * 32 + ((lane & 1) << 4) + (lane >> 1)] = tt;

            float mn = dot4(tt, tt);
#pragma unroll
            for (int o = 16; o; o >>= 1) mn += __shfl_xor_sync(0xffffffffu, mn, o);

            float sv = (lane < CSQ) ? __ldcg(&g_ssp[c * CSQ + lane]) : 0.f;
            int   cv = (lane < CSQ) ? __ldcg(&g_cntp[c * CSQ + lane]) : 0;
#pragma unroll
            for (int o = 2; o; o >>= 1) {
                sv += __shfl_xor_sync(0xffffffffu, sv, o);
                cv += __shfl_xor_sync(0xffffffffu, cv, o);
            }
            if (lane == 0) {
                float cnf = (float)cv;
                float iv  = 1.f / (cnf - 1.f);
                g_mn[c]   = mn;
                g_cntf[c] = cnf;
                g_inv[c]  = iv;
                g_A[c]    = -0.5f * cnf * iv;
                g_B[c]    = -0.5f * sv * iv;
                g_cdone[c] = 0;                 // reset for next graph replay
            }
        }
    }
}

// ---------------------------------------------------------------------------
// 1024 blocks x 128 threads. Warp w = (query-pair pw = w&1, class-half
// ch = w>>1): 16 lanes per query (dims 8i..8i+7), 32 classes per warp ->
// v[32] (~80 regs, 6 CTAs/SM) AND both 16-lane groups read identical mu
// addresses (256B-unique LDGs, R10-level L1 traffic). Halves merge partial
// LSE/dm via 4 floats of smem per query. Fused mean via last-block.
__global__ void __launch_bounds__(128, 6) k_query(
    const float4* __restrict__ xq4, const int* __restrict__ yq,
    const float4* __restrict__ xs4, const int* __restrict__ ys,
    const int* __restrict__ pos, float* __restrict__ out)
{
    const int tid  = threadIdx.x;
    const int lane = tid & 31;
    const int w    = tid >> 5;          // warp 0..3
    const int pw   = w & 1;             // query-pair 0/1
    const int ch   = w >> 1;            // class-half 0/1
    const int grp  = lane >> 4;         // query within pair 0/1
    const int i    = lane & 15;         // dim-split (dims 8i .. 8i+7)
    const int q    = blockIdx.x * QPB + 2 * pw + grp;
    const int qidx = 2 * pw + grp;      // 0..3 within block

    __shared__ float s_mx[QPB][2], s_ex[QPB][2], s_dm[QPB][2];
    __shared__ float s_qq[QPB], s_pl[QPB];
    __shared__ int   s_cq[QPB];
    __shared__ float s_res[QPB];
    __shared__ float s_f[128];
    __shared__ int   s_last;

    // ---- per-query loads + scalar reductions (frees sp regs pre-loop) ----
    float4 xr0 = xq4[q * 32 + 2 * i];
    float4 xr1 = xq4[q * 32 + 2 * i + 1];
    const int p   = pos[q];
    const int cq  = ys[p];
    const int yqi = yq[q];
    {
        float4 sp0 = xs4[p * 32 + 2 * i];
        float4 sp1 = xs4[p * 32 + 2 * i + 1];
        float qq  = dot4(xr0, xr0) + dot4(xr1, xr1);
        float tpd = dot4(sp0, sp0) + dot4(sp1, sp1)
                  - 2.f * (dot4(xr0, sp0) + dot4(xr1, sp1));
#pragma unroll
        for (int o = 1; o <= 8; o <<= 1) {
            qq  += __shfl_xor_sync(0xffffffffu, qq, o);
            tpd += __shfl_xor_sync(0xffffffffu, tpd, o);
        }
        if (ch == 0 && i == 0) s_qq[qidx] = qq;
        // exact (i, pos_i) pair logit + patch value (identical in both halves)
        float pair  = -0.5f * fmaxf(qq + tpd, 0.f);
        float delta = ((__ldg(&g_cntf[yqi]) > 1.5f) ? -INFV : 0.f) - pair;
        s_pl[qidx]  = delta;                    // same value from both halves
        if (ch == 0 && i == 0) s_cq[qidx] = cq;
        // keep qq live for nv computation below via shared re-read later:
        // store in register too
        s_f[tid] = qq;                          // scratch reuse (pre-tail)
    }
    float qq = s_f[tid];

    // ---- hot loop: 32 class dots (half ch), dedup'd 256B LDGs ----
    const int cb = ch << 5;
    float v[32];
#pragma unroll
    for (int c2 = 0; c2 < 32; ++c2) {
        float4 m0 = __ldg(&g_muI[(cb + c2) * 32 + i]);
        float4 m1 = __ldg(&g_muI[(cb + c2) * 32 + 16 + i]);
        v[c2] = fma4(m1, xr1, fma4(m0, xr0, 0.f));
    }

    // ---- recursive-halving exchange within 16 lanes: 30 shfl ----
#pragma unroll
    for (int s = 0; s < 4; ++s) {
        const int o  = 1 << s;
        const int hn = 16 >> s;                 // 16,8,4,2
        const bool up = (i & o) != 0;
#pragma unroll
        for (int j = 0; j < hn; ++j) {
            float send = up ? v[j] : v[j + hn];
            float keep = up ? v[j + hn] : v[j];
            v[j] = keep + __shfl_xor_sync(0xffffffffu, send, o);
        }
    }
    // lane owns classes clb, clb+1 (verified mapping, R15 rel_err == 0)
    const int clb = cb + (((i & 1) << 4) | ((i & 2) << 2) | (i & 4) | ((i & 8) >> 2));

    // normalized logits + patch; extract raw dot(x, mu_cq) if owned
    float dm = 0.f;
    float patch = s_pl[qidx] * __ldg(&g_inv[cq]);
    float nv0, nv1;
    {
        int c0 = clb, c1 = clb + 1;
        nv0 = fmaf(v[0], __ldg(&g_inv[c0]), fmaf(__ldg(&g_A[c0]), qq, __ldg(&g_B[c0])));
        nv1 = fmaf(v[1], __ldg(&g_inv[c1]), fmaf(__ldg(&g_A[c1]), qq, __ldg(&g_B[c1])));
        if (c0 == cq) { dm = v[0]; nv0 += patch; }
        if (c1 == cq) { dm = v[1]; nv1 += patch; }
    }
#pragma unroll
    for (int o = 1; o <= 8; o <<= 1) dm += __shfl_xor_sync(0xffffffffu, dm, o);

    // ---- partial LSE over this half's 32 classes ----
    float mx = fmaxf(nv0, nv1);
#pragma unroll
    for (int o = 1; o <= 8; o <<= 1)
        mx = fmaxf(mx, __shfl_xor_sync(0xffffffffu, mx, o));
    float ex = __expf(nv0 - mx) + __expf(nv1 - mx);
#pragma unroll
    for (int o = 1; o <= 8; o <<= 1)
        ex += __shfl_xor_sync(0xffffffffu, ex, o);

    if (i == 0) {
        s_mx[qidx][ch] = mx;
        s_ex[qidx][ch] = ex;
        s_dm[qidx][ch] = dm;
    }
    __syncthreads();

    // ---- combine halves: 4 threads, one query each ----
    if (tid < QPB) {
        float m0 = s_mx[tid][0], m1 = s_mx[tid][1];
        float m  = fmaxf(m0, m1);
        float e  = s_ex[tid][0] * __expf(m0 - m) + s_ex[tid][1] * __expf(m1 - m);
        float dmt = s_dm[tid][0] + s_dm[tid][1];
        float qqt = s_qq[tid];
        int   cqt = s_cq[tid];
        float cnq = __ldg(&g_cntf[cqt]);
        float den = fmaxf(cnq - 1.f, 0.1f);
        float ee  = den + 1.f;
        float d2  = (ee * ee * qqt - 2.f * ee * dmt + __ldg(&g_mn[cqt])) / (den * den);
        float plog = -sqrtf(fmaxf(d2, 0.f));
        s_res[tid] = (m + __logf(e)) - plog;
    }
    __syncthreads();

    // ---- fused mean: block -> last-block ----
    if (tid == 0) {
        g_bsum[blockIdx.x] = s_res[0] + s_res[1] + s_res[2] + s_res[3];
        __threadfence();
        int old = atomicAdd(&g_done, 1);
        s_last = (old == NBLK - 1);
    }
    __syncthreads();
    if (s_last) {
        __threadfence();
        float acc = 0.f;
#pragma unroll
        for (int it = 0; it < NBLK / 128; ++it) {
            float u;
            asm volatile("ld.global.cg.f32 %0, [%1];"
                         : "=f"(u) : "l"(&g_bsum[tid + it * 128]));
            acc += u;
        }
        s_f[tid] = acc;
        __syncthreads();
#pragma unroll
        for (int o = 64; o; o >>= 1) {
            if (tid < o) s_f[tid] += s_f[tid + o];
            __syncthreads();
        }
        if (tid == 0) {
            out[0] = s_f[0] * (1.0f / (float)NQ_);
            g_done = 0;                         // reset for next graph replay
        }
    }
}

// ---------------------------------------------------------------------------
extern "C" void kernel_launch(void* const* d_in, const int* in_sizes, int n_in,
                              void* d_out, int out_size) {
    const float4* xq4 = (const float4*)d_in[0];   // [NQ, D] f32
    const int*    yqp = (const int*)   d_in[1];   // [NQ]    i32
    const float4* xs4 = (const float4*)d_in[2];   // [NS, D] f32
    const int*    ysp = (const int*)   d_in[3];   // [NS]    i32
    const int*    pop = (const int*)   d_in[4];   // [NQ]    i32
    (void)in_sizes; (void)n_in; (void)out_size;

    k_classsum<<<CSBLK, 512>>>(xs4, ysp);
    k_query<<<NBLK, 128>>>(xq4, yqp, xs4, ysp, pop, (float*)d_out);
}